// round 12
// baseline (speedup 1.0000x reference)
#include <cuda_runtime.h>
#include <math.h>
#include <cstdint>

typedef unsigned long long ull;

// Problem constants
#define L_STEPS 128
#define NB 64
#define HID 4096            // 32*16*8
#define T1S 128             // t1 row stride (words)

__device__ __forceinline__ void fma2(ull& acc, ull a, ull b) {
    asm("fma.rn.f32x2 %0, %1, %2, %0;" : "+l"(acc) : "l"(a), "l"(b));
}
__device__ __forceinline__ ull dup2(float x) {
    ull r; asm("mov.b64 %0, {%1, %1};" : "=l"(r) : "f"(x)); return r;
}
__device__ __forceinline__ ull pack2(float lo, float hi) {
    ull r; asm("mov.b64 %0, {%1, %2};" : "=l"(r) : "f"(lo), "f"(hi)); return r;
}
__device__ __forceinline__ void unpack2(float& lo, float& hi, ull v) {
    asm("mov.b64 {%0, %1}, %2;" : "=f"(lo), "=f"(hi) : "l"(v));
}
__device__ __forceinline__ uint32_t smem_u32(const void* p) {
    uint32_t a;
    asm("{ .reg .u64 t; cvta.to.shared.u64 t, %1; cvt.u32.u64 %0, t; }" : "=r"(a) : "l"(p));
    return a;
}
__device__ __forceinline__ uint32_t mapa_u32(uint32_t addr, uint32_t rank) {
    uint32_t r;
    asm("mapa.shared::cluster.u32 %0, %1, %2;" : "=r"(r) : "r"(addr), "r"(rank));
    return r;
}
__device__ __forceinline__ void st_cluster_b64(uint32_t addr, ull v) {
    asm volatile("st.shared::cluster.b64 [%0], %1;" :: "r"(addr), "l"(v) : "memory");
}

// SMEM layout (floats)
#define SM_H0    0
#define SM_H1    4096
#define SM_T1C   8192      // 48*T1S
#define SM_T1P   14336     // 48*T1S
#define SM_XS    20480     // 2 x 4096 (x[l] ring)
#define SM_XWB   28672     // 2 x 6144 (XW ring: [g*2048 + q*8 + f], q = dd*16+e local)
#define SM_U1T   40960     // 1536: u1t[a*48 + g*16+dd] = U1[g, rank*16+dd, a]
#define SM_W1T   42496     // 1536: same for W1
#define SM_W2T   44032     // 768:  w2t[g*256 + b*16 + e] = U2[g,e,b]
#define SM_W2W   44800     // 768:  same for W2
#define SM_U3S   45568     // 192
#define SM_W3S   45760     // 192
#define SM_TOTAL 45952

// ---------------------------------------------------------------------------
// Fused kernel: producer warps (16-31) compute XW[l+1] into an SMEM ring while
// consumer warps (0-15) run GRU step l. Cluster of 2 CTAs per sample; each CTA
// owns d in [rank*16, rank*16+16). XW never touches global memory.
// ---------------------------------------------------------------------------
__global__ __launch_bounds__(1024) __cluster_dims__(2, 1, 1)
void gru_fused_kernel(
    const float* __restrict__ x,    // (N, L, 4096)
    const float* __restrict__ W1,   // (3,32,32)
    const float* __restrict__ W2,   // (3,16,16)
    const float* __restrict__ W3,   // (3,8,8)
    const float* __restrict__ U1,   // (3,32,32)
    const float* __restrict__ U2,   // (3,16,16)
    const float* __restrict__ U3,   // (3,8,8)
    float* __restrict__ out)        // outs (N,L,4096) then h_last (N,4096)
{
    extern __shared__ float sm[];
    float* h0  = sm + SM_H0;
    float* h1  = sm + SM_H1;
    float* t1c = sm + SM_T1C;
    float* t1p = sm + SM_T1P;
    float* xs  = sm + SM_XS;
    float* xwb = sm + SM_XWB;
    float* u1t = sm + SM_U1T;
    float* w1t = sm + SM_W1T;
    float* w2t = sm + SM_W2T;
    float* w2w = sm + SM_W2W;
    float* u3s = sm + SM_U3S;
    float* w3s = sm + SM_W3S;

    const int t    = threadIdx.x;
    const int n    = blockIdx.x >> 1;
    const int rank = blockIdx.x & 1;
    const int peer = rank ^ 1;

    // ---- init ----
    for (int i = t; i < 4096; i += 1024) h0[i] = 0.f;
    for (int i = t; i < 1536; i += 1024) {
        int g = i >> 9, rem = i & 511, dd = rem >> 5, a = rem & 31;
        int src = ((g * 32) + rank * 16 + dd) * 32 + a;
        int dst = a * 48 + g * 16 + dd;
        u1t[dst] = U1[src];
        w1t[dst] = W1[src];
    }
    if (t < 768) {
        int g = t >> 8, rem = t & 255, e = rem >> 4, b = rem & 15;
        w2t[g * 256 + b * 16 + e] = U2[t];
        w2w[g * 256 + b * 16 + e] = W2[t];
    }
    if (t < 192) { u3s[t] = U3[t]; w3s[t] = W3[t]; }
    // x[0] -> xs slot0, x[1] -> xs slot1 (contiguous 8192 floats)
    {
        const float4* xg4 = reinterpret_cast<const float4*>(x + (size_t)n * L_STEPS * HID);
        float4* xs4 = reinterpret_cast<float4*>(xs);
        xs4[t] = xg4[t];
        xs4[t + 1024] = xg4[t + 1024];
    }
    __syncthreads();

    const uint32_t h0a = smem_u32(h0);
    const uint32_t h1a = smem_u32(h1);

    const int warp = t >> 5, lane = t & 31;
    const int bc0 = lane * 4;               // p1 lane -> 4 cols
    const int e2 = lane >> 1;               // p2/p3 lane -> e
    const int c4 = (lane & 1) * 4;          // p2 column half
    const int f0 = c4;                      // p3 f half
    const bool loLane = ((lane & 1) == 0);

    // consumer p2p3: warp = dd (0..15)
    const int gbase = ((rank * 16 + warp) * 16 + e2) * 8 + f0;
    // producer p2p3: dd = warp-16
    const int pdd = warp - 16;

    // ---- prologue: produce XW[0] into xwb slot 0 from xs slot 0 ----
    if (warp >= 16 && warp < 28) {
        const int r0 = (warp - 16) * 4;
        ull acc2[4][2];
#pragma unroll
        for (int j = 0; j < 4; j++) { acc2[j][0] = 0; acc2[j][1] = 0; }
#pragma unroll
        for (int a = 0; a < 32; a++) {
            ulonglong2 xv = *reinterpret_cast<const ulonglong2*>(&xs[a * 128 + bc0]);
            float4 wv = *reinterpret_cast<const float4*>(&w1t[a * 48 + r0]);
            ull w0 = dup2(wv.x), w1 = dup2(wv.y), w2 = dup2(wv.z), w3 = dup2(wv.w);
            fma2(acc2[0][0], w0, xv.x);  fma2(acc2[0][1], w0, xv.y);
            fma2(acc2[1][0], w1, xv.x);  fma2(acc2[1][1], w1, xv.y);
            fma2(acc2[2][0], w2, xv.x);  fma2(acc2[2][1], w2, xv.y);
            fma2(acc2[3][0], w3, xv.x);  fma2(acc2[3][1], w3, xv.y);
        }
#pragma unroll
        for (int j = 0; j < 4; j++) {
            ulonglong2 st; st.x = acc2[j][0]; st.y = acc2[j][1];
            *reinterpret_cast<ulonglong2*>(&t1p[(r0 + j) * T1S + bc0]) = st;
        }
    }
    __syncthreads();
    if (warp >= 16) {
#pragma unroll
        for (int g = 0; g < 3; g++) {
            const float* t1r = t1p + (g * 16 + pdd) * T1S;
            const float* w2g = w2w + g * 256;
            ull a0 = 0, a1 = 0;
#pragma unroll
            for (int b = 0; b < 16; b++) {
                ulonglong2 tv = *reinterpret_cast<const ulonglong2*>(&t1r[b * 8 + c4]);
                ull wd = dup2(w2g[b * 16 + e2]);
                fma2(a0, wd, tv.x);
                fma2(a1, wd, tv.y);
            }
            float m0, m1, m2, m3;
            unpack2(m0, m1, a0); unpack2(m2, m3, a1);
            float o0 = __shfl_xor_sync(0xffffffffu, m0, 1);
            float o1 = __shfl_xor_sync(0xffffffffu, m1, 1);
            float o2 = __shfl_xor_sync(0xffffffffu, m2, 1);
            float o3 = __shfl_xor_sync(0xffffffffu, m3, 1);
            float col[8];
            col[0] = loLane ? m0 : o0;  col[1] = loLane ? m1 : o1;
            col[2] = loLane ? m2 : o2;  col[3] = loLane ? m3 : o3;
            col[4] = loLane ? o0 : m0;  col[5] = loLane ? o1 : m1;
            col[6] = loLane ? o2 : m2;  col[7] = loLane ? o3 : m3;
            const float* w3g = w3s + g * 64;
            float o[4];
#pragma unroll
            for (int j = 0; j < 4; j++) {
                float4 ua = *reinterpret_cast<const float4*>(&w3g[(f0 + j) * 8]);
                float4 ub = *reinterpret_cast<const float4*>(&w3g[(f0 + j) * 8 + 4]);
                o[j] = ua.x * col[0] + ua.y * col[1] + ua.z * col[2] + ua.w * col[3]
                     + ub.x * col[4] + ub.y * col[5] + ub.z * col[6] + ub.w * col[7];
            }
            *reinterpret_cast<float4*>(&xwb[g * 2048 + (pdd * 16 + e2) * 8 + f0]) =
                make_float4(o[0], o[1], o[2], o[3]);
        }
    }
    __syncthreads();

    float* hc = h0;
    float* hn = h1;

    for (int l = 0; l < L_STEPS; l++) {
        // =========== phase A ===========
        if (warp < 12) {
            // consumer p1: t1c[r][bc] = sum_a u1t[a][r]*hc[a*128+bc]
            const int r0 = warp * 4;
            ull acc2[4][2];
#pragma unroll
            for (int j = 0; j < 4; j++) { acc2[j][0] = 0; acc2[j][1] = 0; }
#pragma unroll
            for (int a = 0; a < 32; a++) {
                ulonglong2 hv = *reinterpret_cast<const ulonglong2*>(&hc[a * 128 + bc0]);
                float4 wv = *reinterpret_cast<const float4*>(&u1t[a * 48 + r0]);
                ull w0 = dup2(wv.x), w1 = dup2(wv.y), w2 = dup2(wv.z), w3 = dup2(wv.w);
                fma2(acc2[0][0], w0, hv.x);  fma2(acc2[0][1], w0, hv.y);
                fma2(acc2[1][0], w1, hv.x);  fma2(acc2[1][1], w1, hv.y);
                fma2(acc2[2][0], w2, hv.x);  fma2(acc2[2][1], w2, hv.y);
                fma2(acc2[3][0], w3, hv.x);  fma2(acc2[3][1], w3, hv.y);
            }
#pragma unroll
            for (int j = 0; j < 4; j++) {
                ulonglong2 st; st.x = acc2[j][0]; st.y = acc2[j][1];
                *reinterpret_cast<ulonglong2*>(&t1c[(r0 + j) * T1S + bc0]) = st;
            }
        } else if (warp < 16) {
            // x prefetch: x[l+2] -> xs slot (l&1)
            if (l + 2 < L_STEPS) {
                const int tt = t - 384;     // 0..127
                const float4* src = reinterpret_cast<const float4*>(
                    x + ((size_t)n * L_STEPS + (l + 2)) * HID);
                float4* dst = reinterpret_cast<float4*>(xs + (l & 1) * 4096);
#pragma unroll
                for (int j = 0; j < 8; j++) {
                    int q = j * 128 + tt;
                    dst[q] = src[q];
                }
            }
        } else if (warp < 28) {
            // producer p1x: t1p[r][bc] = sum_a w1t[a][r]*xcur[a*128+bc]
            if (l + 1 < L_STEPS) {
                const float* xc = xs + ((l + 1) & 1) * 4096;
                const int r0 = (warp - 16) * 4;
                ull acc2[4][2];
#pragma unroll
                for (int j = 0; j < 4; j++) { acc2[j][0] = 0; acc2[j][1] = 0; }
#pragma unroll
                for (int a = 0; a < 32; a++) {
                    ulonglong2 xv = *reinterpret_cast<const ulonglong2*>(&xc[a * 128 + bc0]);
                    float4 wv = *reinterpret_cast<const float4*>(&w1t[a * 48 + r0]);
                    ull w0 = dup2(wv.x), w1 = dup2(wv.y), w2 = dup2(wv.z), w3 = dup2(wv.w);
                    fma2(acc2[0][0], w0, xv.x);  fma2(acc2[0][1], w0, xv.y);
                    fma2(acc2[1][0], w1, xv.x);  fma2(acc2[1][1], w1, xv.y);
                    fma2(acc2[2][0], w2, xv.x);  fma2(acc2[2][1], w2, xv.y);
                    fma2(acc2[3][0], w3, xv.x);  fma2(acc2[3][1], w3, xv.y);
                }
#pragma unroll
                for (int j = 0; j < 4; j++) {
                    ulonglong2 st; st.x = acc2[j][0]; st.y = acc2[j][1];
                    *reinterpret_cast<ulonglong2*>(&t1p[(r0 + j) * T1S + bc0]) = st;
                }
            }
        }
        __syncthreads();

        // =========== phase B ===========
        if (warp < 16) {
            // consumer p2+p3 (register t2 via shuffle) + gate combine
            float hu[3][4];
#pragma unroll
            for (int g = 0; g < 3; g++) {
                const float* t1r = t1c + (g * 16 + warp) * T1S;
                const float* w2g = w2t + g * 256;
                ull a0 = 0, a1 = 0;
#pragma unroll
                for (int b = 0; b < 16; b++) {
                    ulonglong2 tv = *reinterpret_cast<const ulonglong2*>(&t1r[b * 8 + c4]);
                    ull wd = dup2(w2g[b * 16 + e2]);
                    fma2(a0, wd, tv.x);
                    fma2(a1, wd, tv.y);
                }
                float m0, m1, m2, m3;
                unpack2(m0, m1, a0); unpack2(m2, m3, a1);
                float o0 = __shfl_xor_sync(0xffffffffu, m0, 1);
                float o1 = __shfl_xor_sync(0xffffffffu, m1, 1);
                float o2 = __shfl_xor_sync(0xffffffffu, m2, 1);
                float o3 = __shfl_xor_sync(0xffffffffu, m3, 1);
                float col[8];
                col[0] = loLane ? m0 : o0;  col[1] = loLane ? m1 : o1;
                col[2] = loLane ? m2 : o2;  col[3] = loLane ? m3 : o3;
                col[4] = loLane ? o0 : m0;  col[5] = loLane ? o1 : m1;
                col[6] = loLane ? o2 : m2;  col[7] = loLane ? o3 : m3;
                const float* u3g = u3s + g * 64;
#pragma unroll
                for (int j = 0; j < 4; j++) {
                    float4 ua = *reinterpret_cast<const float4*>(&u3g[(f0 + j) * 8]);
                    float4 ub = *reinterpret_cast<const float4*>(&u3g[(f0 + j) * 8 + 4]);
                    hu[g][j] = ua.x * col[0] + ua.y * col[1] + ua.z * col[2] + ua.w * col[3]
                             + ub.x * col[4] + ub.y * col[5] + ub.z * col[6] + ub.w * col[7];
                }
            }
            // XW for this step from SMEM ring
            const float* xwc = xwb + (l & 1) * 6144 + (warp * 16 + e2) * 8 + f0;
            float4 xf0 = *reinterpret_cast<const float4*>(xwc);
            float4 xf1 = *reinterpret_cast<const float4*>(xwc + 2048);
            float4 xf2 = *reinterpret_cast<const float4*>(xwc + 4096);

            float4 ho = *reinterpret_cast<const float4*>(&hc[gbase]);
            float hold[4] = {ho.x, ho.y, ho.z, ho.w};
            float xz[4] = {xf0.x, xf0.y, xf0.z, xf0.w};
            float xr[4] = {xf1.x, xf1.y, xf1.z, xf1.w};
            float xh[4] = {xf2.x, xf2.y, xf2.z, xf2.w};

            float res[4];
#pragma unroll
            for (int j = 0; j < 4; j++) {
                float z  = 1.f / (1.f + __expf(-(xz[j] + hu[0][j])));
                float r  = 1.f / (1.f + __expf(-(xr[j] + hu[1][j])));
                float ax = xh[j] + r * hu[2][j];
                float e2x = __expf(2.f * ax);
                float hh = 1.f - 2.f / (e2x + 1.f);      // tanh, NaN-safe
                res[j] = z * hold[j] + (1.f - z) * hh;
            }
            float4 r4 = make_float4(res[0], res[1], res[2], res[3]);
            *reinterpret_cast<float4*>(&hn[gbase]) = r4;

            // publish to peer's hn via DSMEM
            uint32_t hna = (l & 1) ? h0a : h1a;
            uint32_t ra = mapa_u32(hna + (uint32_t)gbase * 4u, (uint32_t)peer);
            st_cluster_b64(ra,     pack2(res[0], res[1]));
            st_cluster_b64(ra + 8, pack2(res[2], res[3]));

            asm volatile("barrier.cluster.arrive.aligned;" ::: "memory");
            *reinterpret_cast<float4*>(out + ((size_t)n * L_STEPS + l) * HID + gbase) = r4;
        } else {
            // producer p2x+p3x -> xwb slot (l+1)&1
            if (l + 1 < L_STEPS) {
                float* xwp = xwb + ((l + 1) & 1) * 6144;
#pragma unroll
                for (int g = 0; g < 3; g++) {
                    const float* t1r = t1p + (g * 16 + pdd) * T1S;
                    const float* w2g = w2w + g * 256;
                    ull a0 = 0, a1 = 0;
#pragma unroll
                    for (int b = 0; b < 16; b++) {
                        ulonglong2 tv = *reinterpret_cast<const ulonglong2*>(&t1r[b * 8 + c4]);
                        ull wd = dup2(w2g[b * 16 + e2]);
                        fma2(a0, wd, tv.x);
                        fma2(a1, wd, tv.y);
                    }
                    float m0, m1, m2, m3;
                    unpack2(m0, m1, a0); unpack2(m2, m3, a1);
                    float o0 = __shfl_xor_sync(0xffffffffu, m0, 1);
                    float o1 = __shfl_xor_sync(0xffffffffu, m1, 1);
                    float o2 = __shfl_xor_sync(0xffffffffu, m2, 1);
                    float o3 = __shfl_xor_sync(0xffffffffu, m3, 1);
                    float col[8];
                    col[0] = loLane ? m0 : o0;  col[1] = loLane ? m1 : o1;
                    col[2] = loLane ? m2 : o2;  col[3] = loLane ? m3 : o3;
                    col[4] = loLane ? o0 : m0;  col[5] = loLane ? o1 : m1;
                    col[6] = loLane ? o2 : m2;  col[7] = loLane ? o3 : m3;
                    const float* w3g = w3s + g * 64;
                    float o[4];
#pragma unroll
                    for (int j = 0; j < 4; j++) {
                        float4 ua = *reinterpret_cast<const float4*>(&w3g[(f0 + j) * 8]);
                        float4 ub = *reinterpret_cast<const float4*>(&w3g[(f0 + j) * 8 + 4]);
                        o[j] = ua.x * col[0] + ua.y * col[1] + ua.z * col[2] + ua.w * col[3]
                             + ub.x * col[4] + ub.y * col[5] + ub.z * col[6] + ub.w * col[7];
                    }
                    *reinterpret_cast<float4*>(&xwp[g * 2048 + (pdd * 16 + e2) * 8 + f0]) =
                        make_float4(o[0], o[1], o[2], o[3]);
                }
            }
            asm volatile("barrier.cluster.arrive.aligned;" ::: "memory");
        }
        asm volatile("barrier.cluster.wait.aligned;" ::: "memory");

        float* tmp = hc; hc = hn; hn = tmp;
    }

    // h_last: each CTA writes its own half
    float* hl = out + (size_t)NB * L_STEPS * HID + (size_t)n * HID + rank * 2048;
    const float* hsrc = hc + rank * 2048;
    for (int i = t; i < 2048; i += 1024) hl[i] = hsrc[i];
}

// ---------------------------------------------------------------------------
extern "C" void kernel_launch(void* const* d_in, const int* in_sizes, int n_in,
                              void* d_out, int out_size)
{
    const float* x  = (const float*)d_in[0];
    const float* W1 = (const float*)d_in[1];
    const float* W2 = (const float*)d_in[2];
    const float* W3 = (const float*)d_in[3];
    const float* U1 = (const float*)d_in[4];
    const float* U2 = (const float*)d_in[5];
    const float* U3 = (const float*)d_in[6];
    float* out = (float*)d_out;

    const int SMEM = SM_TOTAL * (int)sizeof(float);   // ~180 KB
    cudaFuncSetAttribute(gru_fused_kernel,
                         cudaFuncAttributeMaxDynamicSharedMemorySize, SMEM);

    gru_fused_kernel<<<NB * 2, 1024, SMEM>>>(x, W1, W2, W3, U1, U2, U3, out);
}